// round 15
// baseline (speedup 1.0000x reference)
#include <cuda_runtime.h>
#include <cuda_fp16.h>
#include <cstdint>
#include <cstddef>

// Problem dims
#define B_DIM 16
#define T_DIM 512
#define D_DIM 256
#define H_DIM 256
#define SCALE_C 0.1f

// HMMA tiling (proven R7): 128x128 tile, K chunks of 64, warp tile 64x32
#define KC 64
#define NCHUNK 4
#define CH_BYTES (128 * 128)
#define SMEM_DYN (4 * CH_BYTES + 1024)

// Hybrid split: HMMA covers n-cols [0, 49152), SIMT covers [49152, 65536)
#define N_SPLIT 49152
#define N_HMMA_BLOCKS 24576            // 64 m-tiles(128) x 384 n-tiles(128)
#define N_SIMT_BLOCKS 16384            // 128 m-tiles(64) x 128 n-tiles(128)
#define N_TOTAL_BLOCKS 40960           // = 5 * 8192, interleave 3 hmma : 2 simt

// ---------------- static device scratch ----------------
__device__ __half g_P[(size_t)B_DIM * T_DIM * H_DIM * H_DIM];   // 1 GB, P[bt][o*256+h]
__device__ __half g_Xh[(size_t)B_DIM * T_DIM * D_DIM];          // 4 MB, x fp16
__device__ __half g_BTh[(size_t)H_DIM * H_DIM * D_DIM];         // 32 MB, B_w^T fp16
__device__ float g_h[2][B_DIM * H_DIM];
__device__ unsigned g_flag[2][64];

// ---------------- helpers ----------------
__device__ __forceinline__ uint32_t smem_u32(const void* p) {
    uint32_t a;
    asm("{ .reg .u64 t; cvta.to.shared.u64 t, %1; cvt.u32.u64 %0, t; }" : "=r"(a) : "l"(p));
    return a;
}
__device__ __forceinline__ uint32_t swz(int row, int kbyte) {
    return (uint32_t)(row * 128 + (kbyte ^ ((row << 4) & 0x70)));
}
__device__ __forceinline__ void cp_async16(uint32_t saddr, const void* gaddr) {
    asm volatile("cp.async.cg.shared.global [%0], [%1], 16;" :: "r"(saddr), "l"(gaddr) : "memory");
}
#define CP_COMMIT() asm volatile("cp.async.commit_group;" ::: "memory")
#define CP_WAIT(n)  asm volatile("cp.async.wait_group %0;" :: "n"(n) : "memory")

__device__ __forceinline__ void ldsm_x4(uint32_t* r, uint32_t addr) {
    asm volatile("ldmatrix.sync.aligned.m8n8.x4.shared.b16 {%0,%1,%2,%3}, [%4];"
                 : "=r"(r[0]), "=r"(r[1]), "=r"(r[2]), "=r"(r[3]) : "r"(addr));
}
__device__ __forceinline__ void ldsm_x2(uint32_t* r, uint32_t addr) {
    asm volatile("ldmatrix.sync.aligned.m8n8.x2.shared.b16 {%0,%1}, [%2];"
                 : "=r"(r[0]), "=r"(r[1]) : "r"(addr));
}
__device__ __forceinline__ void mma16816(float* c, const uint32_t* a, const uint32_t* b) {
    asm volatile("mma.sync.aligned.m16n8k16.row.col.f32.f16.f16.f32 "
                 "{%0,%1,%2,%3}, {%4,%5,%6,%7}, {%8,%9}, {%0,%1,%2,%3};"
                 : "+f"(c[0]), "+f"(c[1]), "+f"(c[2]), "+f"(c[3])
                 : "r"(a[0]), "r"(a[1]), "r"(a[2]), "r"(a[3]), "r"(b[0]), "r"(b[1]));
}

// ---------------- prep kernels ----------------
__global__ void cvt_x_kernel(const float* __restrict__ x) {
    int n = B_DIM * T_DIM * D_DIM;
    for (int i = blockIdx.x * blockDim.x + threadIdx.x; i < n; i += gridDim.x * blockDim.x)
        g_Xh[i] = __float2half_rn(x[i]);
}

__global__ void transpose_B_kernel(const float* __restrict__ Bw) {
    __shared__ float tile[32][33];
    int o = blockIdx.z;
    int h0 = blockIdx.x * 32, d0 = blockIdx.y * 32;
    int tx = threadIdx.x, ty = threadIdx.y;
    #pragma unroll
    for (int i = 0; i < 32; i += 8)
        tile[ty + i][tx] = Bw[(size_t)o * 65536 + (size_t)(d0 + ty + i) * 256 + h0 + tx];
    __syncthreads();
    #pragma unroll
    for (int i = 0; i < 32; i += 8)
        g_BTh[((size_t)o * 256 + h0 + ty + i) * 256 + d0 + tx] = __float2half_rn(tile[tx][ty + i]);
}

// ================= hybrid GEMM kernel =================
// 40960 blocks x 256 threads, interleaved 3 HMMA : 2 SIMT. The two block
// families partition the N range and never synchronize with each other.
__global__ __launch_bounds__(256, 2) void gemm_hybrid_kernel() {
    extern __shared__ char dynsmem[];
    int tid = threadIdx.x;
    int bid = blockIdx.x;
    int g5 = bid / 5, r5 = bid - g5 * 5;

    if (r5 < 3) {
        // ================== HMMA role (R7 body verbatim) ==================
        int idx = g5 * 3 + r5;                 // 0..24575
        int gm0 = (idx & 63) * 128;            // m fast -> B-tile L2 reuse
        int gn0 = (idx >> 6) * 128;

        uint32_t base = (smem_u32(dynsmem) + 1023u) & ~1023u;
        uint32_t aoff[2] = { base, base + CH_BYTES };
        uint32_t boff[2] = { base + 2 * CH_BYTES, base + 3 * CH_BYTES };

        int wid = tid >> 5, lane = tid & 31;
        int wm = (wid >> 2) * 64;
        int wn = (wid & 3) * 32;

        const __half* Asrc = g_Xh + (size_t)gm0 * 256;
        const __half* Bsrc = g_BTh + (size_t)gn0 * 256;

        auto load_chunk = [&](int kc, int buf) {
            int k0 = kc * KC;
            #pragma unroll
            for (int it = 0; it < 4; it++) {
                int i = tid + it * 256;
                int r = i >> 3, c16 = i & 7;
                cp_async16(aoff[buf] + swz(r, c16 * 16), &Asrc[(size_t)r * 256 + k0 + c16 * 8]);
            }
            #pragma unroll
            for (int it = 0; it < 4; it++) {
                int i = tid + it * 256;
                int r = i >> 3, c16 = i & 7;
                cp_async16(boff[buf] + swz(r, c16 * 16), &Bsrc[(size_t)r * 256 + k0 + c16 * 8]);
            }
            CP_COMMIT();
        };

        float acc[4][4][4];
        #pragma unroll
        for (int mi = 0; mi < 4; mi++)
            #pragma unroll
            for (int ni = 0; ni < 4; ni++)
                #pragma unroll
                for (int e = 0; e < 4; e++) acc[mi][ni][e] = 0.f;

        int la = (lane & 7) + ((lane >> 3) & 1) * 8;
        int ka = ((lane >> 4) & 1) * 8;
        int lb = lane & 7;
        int kb = ((lane >> 3) & 1) * 8;

        load_chunk(0, 0);

        #pragma unroll
        for (int kc = 0; kc < NCHUNK; kc++) {
            int buf = kc & 1;
            if (kc + 1 < NCHUNK) load_chunk(kc + 1, (kc + 1) & 1);
            if (kc + 1 < NCHUNK) { CP_WAIT(1); } else { CP_WAIT(0); }
            __syncthreads();

            uint32_t ab = aoff[buf], bb = boff[buf];
            #pragma unroll
            for (int ks = 0; ks < 4; ks++) {
                uint32_t afr[4][4], bfr[4][2];
                #pragma unroll
                for (int mi = 0; mi < 4; mi++) {
                    int row = wm + mi * 16 + la;
                    ldsm_x4(afr[mi], ab + swz(row, (ks * 16 + ka) * 2));
                }
                #pragma unroll
                for (int ni = 0; ni < 4; ni++) {
                    int row = wn + ni * 8 + lb;
                    ldsm_x2(bfr[ni], bb + swz(row, (ks * 16 + kb) * 2));
                }
                #pragma unroll
                for (int mi = 0; mi < 4; mi++)
                    #pragma unroll
                    for (int ni = 0; ni < 4; ni++)
                        mma16816(acc[mi][ni], afr[mi], bfr[ni]);
            }
            __syncthreads();
        }

        {
            __half* sm = (__half*)dynsmem;
            int q = lane >> 2, p = lane & 3;
            #pragma unroll
            for (int mi = 0; mi < 4; mi++)
                #pragma unroll
                for (int ni = 0; ni < 4; ni++) {
                    int col = wn + ni * 8 + p * 2;
                    int r0 = wm + mi * 16 + q;
                    *(__half2*)&sm[r0 * 136 + col] =
                        __floats2half2_rn(acc[mi][ni][0], acc[mi][ni][1]);
                    *(__half2*)&sm[(r0 + 8) * 136 + col] =
                        __floats2half2_rn(acc[mi][ni][2], acc[mi][ni][3]);
                }
            __syncthreads();
            #pragma unroll
            for (int j = 0; j < 8; j++) {
                int i = tid + j * 256;
                int r = i >> 4, c16 = i & 15;
                uint4 v = *(const uint4*)&sm[r * 136 + c16 * 8];
                *(uint4*)&g_P[(size_t)(gm0 + r) * 65536 + gn0 + c16 * 8] = v;
            }
        }
        return;
    }

    // ================== SIMT role (HFMA2 on the fma pipe) ==================
    // Tile 64(M) x 128(N), K chunks of 64. smem k-pair-major:
    //   As[kpl][m] (32x64 half2), Bs[kpl][n] (32x128 half2); single buffer,
    //   next chunk prefetched to registers during compute.
    {
        int idx = g5 * 2 + (r5 - 3);           // 0..16383
        int gm0 = (idx & 127) * 64;
        int gn0 = N_SPLIT + (idx >> 7) * 128;

        uint32_t* As = (uint32_t*)dynsmem;             // 32*64 half2 = 8 KB
        uint32_t* Bs = (uint32_t*)(dynsmem + 8192);    // 32*128 half2 = 16 KB

        const __half* Asrc = g_Xh + (size_t)gm0 * 256;
        const __half* Bsrc = g_BTh + (size_t)gn0 * 256;

        int tm = tid >> 4;                     // 0..15 -> 4 m-rows each
        int tn = tid & 15;                     // 0..15 -> 8 n-cols each

        uint4 pa[2], pb[4];
        auto ldg_chunk = [&](int kc) {
            int k0 = kc * 64;
            #pragma unroll
            for (int it = 0; it < 2; it++) {   // A: 64 rows x 8 segs
                int s = tid + it * 256;
                int r = s >> 3, c8 = s & 7;
                pa[it] = *(const uint4*)&Asrc[(size_t)r * 256 + k0 + c8 * 8];
            }
            #pragma unroll
            for (int it = 0; it < 4; it++) {   // B: 128 rows x 8 segs
                int s = tid + it * 256;
                int r = s >> 3, c8 = s & 7;
                pb[it] = *(const uint4*)&Bsrc[(size_t)r * 256 + k0 + c8 * 8];
            }
        };
        auto sts_chunk = [&]() {
            #pragma unroll
            for (int it = 0; it < 2; it++) {
                int s = tid + it * 256;
                int r = s >> 3, c8 = s & 7;
                As[(c8 * 4 + 0) * 64 + r] = pa[it].x;
                As[(c8 * 4 + 1) * 64 + r] = pa[it].y;
                As[(c8 * 4 + 2) * 64 + r] = pa[it].z;
                As[(c8 * 4 + 3) * 64 + r] = pa[it].w;
            }
            #pragma unroll
            for (int it = 0; it < 4; it++) {
                int s = tid + it * 256;
                int r = s >> 3, c8 = s & 7;
                Bs[(c8 * 4 + 0) * 128 + r] = pb[it].x;
                Bs[(c8 * 4 + 1) * 128 + r] = pb[it].y;
                Bs[(c8 * 4 + 2) * 128 + r] = pb[it].z;
                Bs[(c8 * 4 + 3) * 128 + r] = pb[it].w;
            }
        };

        __half2 ch[4][8];
        float accf[4][8];
        const __half2 hz = __float2half2_rn(0.f);
        #pragma unroll
        for (int i = 0; i < 4; i++)
            #pragma unroll
            for (int j = 0; j < 8; j++) { ch[i][j] = hz; accf[i][j] = 0.f; }

        ldg_chunk(0);
        sts_chunk();

        #pragma unroll
        for (int kc = 0; kc < 4; kc++) {
            __syncthreads();                    // smem chunk ready
            if (kc + 1 < 4) ldg_chunk(kc + 1);  // prefetch next to regs

            #pragma unroll
            for (int kpl = 0; kpl < 32; kpl++) {
                uint4 av = *(const uint4*)&As[kpl * 64 + tm * 4];
                uint4 bv0 = *(const uint4*)&Bs[kpl * 128 + tn * 8];
                uint4 bv1 = *(const uint4*)&Bs[kpl * 128 + tn * 8 + 4];
                __half2 a[4] = { *(__half2*)&av.x, *(__half2*)&av.y,
                                 *(__half2*)&av.z, *(__half2*)&av.w };
                __half2 b[8] = { *(__half2*)&bv0.x, *(__half2*)&bv0.y,
                                 *(__half2*)&bv0.z, *(__half2*)&bv0.w,
                                 *(__half2*)&bv1.x, *(__half2*)&bv1.y,
                                 *(__half2*)&bv1.z, *(__half2*)&bv1.w };
                #pragma unroll
                for (int i = 0; i < 4; i++)
                    #pragma unroll
                    for (int j = 0; j < 8; j++)
                        ch[i][j] = __hfma2(a[i], b[j], ch[i][j]);

                if (kpl == 15 || kpl == 31) {   // promote every 32 k (R13-proven)
                    #pragma unroll
                    for (int i = 0; i < 4; i++)
                        #pragma unroll
                        for (int j = 0; j < 8; j++) {
                            float2 f = __half22float2(ch[i][j]);
                            accf[i][j] += f.x + f.y;
                            ch[i][j] = hz;
                        }
                }
            }
            __syncthreads();                    // done reading smem
            if (kc + 1 < 4) sts_chunk();        // store next chunk
        }

        // epilogue: direct coalesced stores (16 threads cover a 128B row segment)
        #pragma unroll
        for (int i = 0; i < 4; i++) {
            int row = gm0 + tm * 4 + i;
            union { __half h[8]; uint4 v; } u;
            #pragma unroll
            for (int j = 0; j < 8; j++) u.h[j] = __float2half_rn(accf[i][j]);
            *(uint4*)&g_P[(size_t)row * 65536 + gn0 + tn * 8] = u.v;
        }
    }
}

// ---------------- fast activations ----------------
__device__ __forceinline__ float sigmoid_fast(float v) { return 1.0f / (1.0f + __expf(-v)); }
__device__ __forceinline__ float tanh_fast(float v)    { return 1.0f - 2.0f / (1.0f + __expf(2.0f * v)); }

// ---------------- persistent scan kernel (proven R8 version) ----------------
__global__ __launch_bounds__(256) void scan_kernel(
    const float* __restrict__ x,
    const float* __restrict__ Ww, const float* __restrict__ Wb,
    const float* __restrict__ Uw, const float* __restrict__ Ub,
    const float* __restrict__ Bbias,
    float* __restrict__ out, int out_size)
{
    __shared__ float Us[16][256];
    __shared__ float Ws[16][256];
    __shared__ float cb_s[16];
    __shared__ float bb_s[4];
    __shared__ unsigned s_base;

    int tid = threadIdx.x;
    int wid = tid >> 5, lane = tid & 31;
    int bid = blockIdx.x;
    int grp = bid >> 6;
    int slot = bid & 63;
    int o0 = slot * 4;
    int b  = grp * 8 + wid;

    if (tid == 0) s_base = *(volatile unsigned*)&g_flag[grp][slot];

    for (int i = tid; i < 4096; i += 256) {
        int r = i >> 8, k = i & 255;
        int p = r >> 2, gi = r & 3;
        int grow = gi * 256 + o0 + p;
        Us[r][k] = Uw[(size_t)grow * 256 + k];
        Ws[r][k] = Ww[(size_t)grow * 256 + k];
    }
    if (tid < 16) {
        int p = tid >> 2, gi = tid & 3;
        int grow = gi * 256 + o0 + p;
        cb_s[tid] = Wb[grow] + Ub[grow];
    }
    if (tid < 4) bb_s[tid] = Bbias[o0 + tid];

    float c[4] = {0.f, 0.f, 0.f, 0.f};
    if (lane < 4) g_h[0][b * 256 + o0 + lane] = 0.f;
    __syncthreads();
    unsigned base = s_base;
    if (tid == 0) {
        __threadfence();
        *(volatile unsigned*)&g_flag[grp][slot] = base + 1;
    }

    int pollidx = tid & 63;
    const volatile unsigned* myflag = &g_flag[grp][pollidx];

    for (int t = 0; t < T_DIM; t++) {
        float xr[8];
        const float* xp = x + ((size_t)b * T_DIM + t) * 256 + lane * 8;
        *(float4*)&xr[0] = *(const float4*)xp;
        *(float4*)&xr[4] = *(const float4*)(xp + 4);

        uint4 pr[4];
        const __half* pp = g_P + (size_t)(b * T_DIM + t) * 65536 + (size_t)o0 * 256 + lane * 8;
        #pragma unroll
        for (int p = 0; p < 4; p++) pr[p] = *(const uint4*)(pp + (size_t)p * 256);

        float gs[16];
        #pragma unroll
        for (int r = 0; r < 16; r++) {
            float4 w0 = *(const float4*)&Ws[r][lane * 8];
            float4 w1 = *(const float4*)&Ws[r][lane * 8 + 4];
            gs[r] = w0.x * xr[0] + w0.y * xr[1] + w0.z * xr[2] + w0.w * xr[3]
                  + w1.x * xr[4] + w1.y * xr[5] + w1.z * xr[6] + w1.w * xr[7];
        }

        {
            unsigned target = base + 1 + (unsigned)t;
            bool ok;
            do {
                unsigned v = *myflag;
                ok = ((int)(v - target) >= 0);
            } while (!__syncthreads_and(ok));
            __threadfence();
        }

        int rb = t & 1;
        float hr[8];
        const float* hp = &g_h[rb][b * 256 + lane * 8];
        *(float4*)&hr[0] = *(const float4*)hp;
        *(float4*)&hr[4] = *(const float4*)(hp + 4);

        #pragma unroll
        for (int r = 0; r < 16; r++) {
            float4 u0 = *(const float4*)&Us[r][lane * 8];
            float4 u1 = *(const float4*)&Us[r][lane * 8 + 4];
            gs[r] += u0.x * hr[0] + u0.y * hr[1] + u0.z * hr[2] + u0.w * hr[3]
                   + u1.x * hr[4] + u1.y * hr[5] + u1.z * hr[6] + u1.w * hr[7];
        }

        float ms[4];
        #pragma unroll
        for (int p = 0; p < 4; p++) {
            const __half2* pb = (const __half2*)&pr[p];
            float s = 0.f;
            #pragma unroll
            for (int j = 0; j < 4; j++) {
                float2 f = __half22float2(pb[j]);
                s += f.x * hr[2 * j] + f.y * hr[2 * j + 1];
            }
            ms[p] = s;
        }

        #pragma unroll
        for (int off = 16; off > 0; off >>= 1) {
            #pragma unroll
            for (int r = 0; r < 16; r++) gs[r] += __shfl_xor_sync(0xffffffffu, gs[r], off);
            #pragma unroll
            for (int p = 0; p < 4; p++) ms[p] += __shfl_xor_sync(0xffffffffu, ms[p], off);
        }

        float hn[4];
        #pragma unroll
        for (int p = 0; p < 4; p++) {
            float iv = sigmoid_fast(gs[p * 4 + 0] + cb_s[p * 4 + 0]);
            float fv = sigmoid_fast(gs[p * 4 + 1] + cb_s[p * 4 + 1]);
            float ov = sigmoid_fast(gs[p * 4 + 2] + cb_s[p * 4 + 2]);
            float gv = tanh_fast(gs[p * 4 + 3] + cb_s[p * 4 + 3]);
            float mv = tanh_fast(ms[p] + bb_s[p]);
            c[p] = fv * c[p] + iv * gv + SCALE_C * mv;
            hn[p] = ov * tanh_fast(c[p]);
        }

        if (lane < 4) {
            float v = hn[lane];
            g_h[rb ^ 1][b * 256 + o0 + lane] = v;
            out[((size_t)b * T_DIM + t) * 256 + o0 + lane] = v;
            if (t == T_DIM - 1) {
                size_t tail = (size_t)B_DIM * T_DIM * H_DIM;
                if (out_size >= (int)(tail + 2 * B_DIM * H_DIM)) {
                    out[tail + b * 256 + o0 + lane] = v;
                    out[tail + B_DIM * H_DIM + b * 256 + o0 + lane] = c[lane];
                }
            }
        }

        __syncthreads();
        if (tid == 0) {
            __threadfence();
            *(volatile unsigned*)&g_flag[grp][slot] = base + 2 + (unsigned)t;
        }
    }
}

// ---------------- launch ----------------
extern "C" void kernel_launch(void* const* d_in, const int* in_sizes, int n_in,
                              void* d_out, int out_size) {
    const float* x  = (const float*)d_in[0];
    const float* Ww = (const float*)d_in[1];
    const float* Wb = (const float*)d_in[2];
    const float* Uw = (const float*)d_in[3];
    const float* Ub = (const float*)d_in[4];
    const float* Bw = (const float*)d_in[5];
    const float* Bb = (const float*)d_in[6];
    float* out = (float*)d_out;

    cudaFuncSetAttribute(gemm_hybrid_kernel, cudaFuncAttributeMaxDynamicSharedMemorySize, SMEM_DYN);

    cvt_x_kernel<<<1024, 512>>>(x);
    transpose_B_kernel<<<dim3(8, 8, 256), dim3(32, 8)>>>(Bw);
    gemm_hybrid_kernel<<<N_TOTAL_BLOCKS, 256, SMEM_DYN>>>();
    scan_kernel<<<128, 256>>>(x, Ww, Wb, Uw, Ub, Bb, out, out_size);
}

// round 16
// speedup vs baseline: 1.2239x; 1.2239x over previous
#include <cuda_runtime.h>
#include <cuda_fp16.h>
#include <cstdint>
#include <cstddef>

// Problem dims
#define B_DIM 16
#define T_DIM 512
#define D_DIM 256
#define H_DIM 256
#define SCALE_C 0.1f

// GEMM tiling (proven R7/R8): 128x128 tile, K chunks of 64, warp tile 64x32
#define KC 64
#define NCHUNK 4
#define CH_BYTES (128 * 128)
#define SMEM_DYN (4 * CH_BYTES + 1024)

// ---------------- static device scratch ----------------
__device__ __half g_P[(size_t)B_DIM * T_DIM * H_DIM * H_DIM];   // 1 GB, P[bt][o*256+h]
__device__ __half g_Xh[(size_t)B_DIM * T_DIM * D_DIM];          // 4 MB, x fp16
__device__ __half g_BTh[(size_t)H_DIM * H_DIM * D_DIM];         // 32 MB, B_w^T fp16
__device__ __half g_Wh[4 * H_DIM * D_DIM];                      // 0.5 MB, W_w fp16 (same layout)
__device__ __half g_Wxh[(size_t)B_DIM * T_DIM * 4 * H_DIM];     // 16 MB, Wx[bt][4H] fp16
__device__ __half g_hh[2][B_DIM * H_DIM];                       // fp16 hidden state (dbl buf)
__device__ unsigned g_flag[2][64];                              // scan arrival flags

// ---------------- helpers ----------------
__device__ __forceinline__ uint32_t smem_u32(const void* p) {
    uint32_t a;
    asm("{ .reg .u64 t; cvta.to.shared.u64 t, %1; cvt.u32.u64 %0, t; }" : "=r"(a) : "l"(p));
    return a;
}
__device__ __forceinline__ uint32_t swz(int row, int kbyte) {
    return (uint32_t)(row * 128 + (kbyte ^ ((row << 4) & 0x70)));
}
__device__ __forceinline__ void cp_async16(uint32_t saddr, const void* gaddr) {
    asm volatile("cp.async.cg.shared.global [%0], [%1], 16;" :: "r"(saddr), "l"(gaddr) : "memory");
}
#define CP_COMMIT() asm volatile("cp.async.commit_group;" ::: "memory")
#define CP_WAIT(n)  asm volatile("cp.async.wait_group %0;" :: "n"(n) : "memory")

__device__ __forceinline__ void ldsm_x4(uint32_t* r, uint32_t addr) {
    asm volatile("ldmatrix.sync.aligned.m8n8.x4.shared.b16 {%0,%1,%2,%3}, [%4];"
                 : "=r"(r[0]), "=r"(r[1]), "=r"(r[2]), "=r"(r[3]) : "r"(addr));
}
__device__ __forceinline__ void ldsm_x2(uint32_t* r, uint32_t addr) {
    asm volatile("ldmatrix.sync.aligned.m8n8.x2.shared.b16 {%0,%1}, [%2];"
                 : "=r"(r[0]), "=r"(r[1]) : "r"(addr));
}
__device__ __forceinline__ void mma16816(float* c, const uint32_t* a, const uint32_t* b) {
    asm volatile("mma.sync.aligned.m16n8k16.row.col.f32.f16.f16.f32 "
                 "{%0,%1,%2,%3}, {%4,%5,%6,%7}, {%8,%9}, {%0,%1,%2,%3};"
                 : "+f"(c[0]), "+f"(c[1]), "+f"(c[2]), "+f"(c[3])
                 : "r"(a[0]), "r"(a[1]), "r"(a[2]), "r"(a[3]), "r"(b[0]), "r"(b[1]));
}

// ---------------- prep kernels ----------------
__global__ void cvt_x_kernel(const float* __restrict__ x, const float* __restrict__ Ww) {
    int n = B_DIM * T_DIM * D_DIM;
    for (int i = blockIdx.x * blockDim.x + threadIdx.x; i < n; i += gridDim.x * blockDim.x)
        g_Xh[i] = __float2half_rn(x[i]);
    int nw = 4 * H_DIM * D_DIM;
    for (int i = blockIdx.x * blockDim.x + threadIdx.x; i < nw; i += gridDim.x * blockDim.x)
        g_Wh[i] = __float2half_rn(Ww[i]);
}

__global__ void transpose_B_kernel(const float* __restrict__ Bw) {
    __shared__ float tile[32][33];
    int o = blockIdx.z;
    int h0 = blockIdx.x * 32, d0 = blockIdx.y * 32;
    int tx = threadIdx.x, ty = threadIdx.y;
    #pragma unroll
    for (int i = 0; i < 32; i += 8)
        tile[ty + i][tx] = Bw[(size_t)o * 65536 + (size_t)(d0 + ty + i) * 256 + h0 + tx];
    __syncthreads();
    #pragma unroll
    for (int i = 0; i < 32; i += 8)
        g_BTh[((size_t)o * 256 + h0 + ty + i) * 256 + d0 + tx] = __float2half_rn(tile[tx][ty + i]);
}

// ---------------- fp16 mma GEMM (R8 body + Wx tiles) ----------------
// Grid (64, 520): by<512 -> P tiles; by>=512 -> Wx tiles (B operand = g_Wh).
__global__ __launch_bounds__(256, 2) void gemm_P_kernel() {
    extern __shared__ char dynsmem[];
    uint32_t base = (smem_u32(dynsmem) + 1023u) & ~1023u;
    uint32_t aoff[2] = { base, base + CH_BYTES };
    uint32_t boff[2] = { base + 2 * CH_BYTES, base + 3 * CH_BYTES };

    int tid = threadIdx.x;
    int wid = tid >> 5, lane = tid & 31;
    int gm0 = blockIdx.x * 128;
    int by = blockIdx.y;

    const __half* Bsrc;
    __half* dst;
    size_t dstStride;
    int col0;
    if (by < 512) {
        Bsrc = g_BTh + (size_t)by * 128 * 256;
        dst = g_P; dstStride = 65536; col0 = by * 128;
    } else {
        Bsrc = g_Wh + (size_t)(by - 512) * 128 * 256;
        dst = g_Wxh; dstStride = 1024; col0 = (by - 512) * 128;
    }

    int wm = (wid >> 2) * 64;
    int wn = (wid & 3) * 32;
    const __half* Asrc = g_Xh + (size_t)gm0 * 256;

    auto load_chunk = [&](int kc, int buf) {
        int k0 = kc * KC;
        #pragma unroll
        for (int it = 0; it < 4; it++) {
            int i = tid + it * 256;
            int r = i >> 3, c16 = i & 7;
            cp_async16(aoff[buf] + swz(r, c16 * 16), &Asrc[(size_t)r * 256 + k0 + c16 * 8]);
        }
        #pragma unroll
        for (int it = 0; it < 4; it++) {
            int i = tid + it * 256;
            int r = i >> 3, c16 = i & 7;
            cp_async16(boff[buf] + swz(r, c16 * 16), &Bsrc[(size_t)r * 256 + k0 + c16 * 8]);
        }
        CP_COMMIT();
    };

    float acc[4][4][4];
    #pragma unroll
    for (int mi = 0; mi < 4; mi++)
        #pragma unroll
        for (int ni = 0; ni < 4; ni++)
            #pragma unroll
            for (int e = 0; e < 4; e++) acc[mi][ni][e] = 0.f;

    int la = (lane & 7) + ((lane >> 3) & 1) * 8;
    int ka = ((lane >> 4) & 1) * 8;
    int lb = lane & 7;
    int kb = ((lane >> 3) & 1) * 8;

    load_chunk(0, 0);

    #pragma unroll
    for (int kc = 0; kc < NCHUNK; kc++) {
        int buf = kc & 1;
        if (kc + 1 < NCHUNK) load_chunk(kc + 1, (kc + 1) & 1);
        if (kc + 1 < NCHUNK) { CP_WAIT(1); } else { CP_WAIT(0); }
        __syncthreads();

        uint32_t ab = aoff[buf], bb = boff[buf];
        #pragma unroll
        for (int ks = 0; ks < 4; ks++) {
            uint32_t afr[4][4], bfr[4][2];
            #pragma unroll
            for (int mi = 0; mi < 4; mi++) {
                int row = wm + mi * 16 + la;
                ldsm_x4(afr[mi], ab + swz(row, (ks * 16 + ka) * 2));
            }
            #pragma unroll
            for (int ni = 0; ni < 4; ni++) {
                int row = wn + ni * 8 + lb;
                ldsm_x2(bfr[ni], bb + swz(row, (ks * 16 + kb) * 2));
            }
            #pragma unroll
            for (int mi = 0; mi < 4; mi++)
                #pragma unroll
                for (int ni = 0; ni < 4; ni++)
                    mma16816(acc[mi][ni], afr[mi], bfr[ni]);
        }
        __syncthreads();
    }

    {
        __half* sm = (__half*)dynsmem;
        int q = lane >> 2, p = lane & 3;
        #pragma unroll
        for (int mi = 0; mi < 4; mi++)
            #pragma unroll
            for (int ni = 0; ni < 4; ni++) {
                int col = wn + ni * 8 + p * 2;
                int r0 = wm + mi * 16 + q;
                *(__half2*)&sm[r0 * 136 + col] =
                    __floats2half2_rn(acc[mi][ni][0], acc[mi][ni][1]);
                *(__half2*)&sm[(r0 + 8) * 136 + col] =
                    __floats2half2_rn(acc[mi][ni][2], acc[mi][ni][3]);
            }
        __syncthreads();
        #pragma unroll
        for (int j = 0; j < 8; j++) {
            int i = tid + j * 256;
            int r = i >> 4, c16 = i & 15;
            uint4 v = *(const uint4*)&sm[r * 136 + c16 * 8];
            *(uint4*)&dst[(size_t)(gm0 + r) * dstStride + col0 + c16 * 8] = v;
        }
    }
}

// ---------------- fast activations ----------------
__device__ __forceinline__ float sigmoid_fast(float v) { return 1.0f / (1.0f + __expf(-v)); }
__device__ __forceinline__ float tanh_fast(float v)    { return 1.0f - 2.0f / (1.0f + __expf(2.0f * v)); }

// ---------------- scan v3: register-resident fp16 U, precomputed Wx, tree reduce ----------------
__global__ __launch_bounds__(256) void scan_kernel(
    const float* __restrict__ Uw, const float* __restrict__ Wb,
    const float* __restrict__ Ub, const float* __restrict__ Bbias,
    float* __restrict__ out, int out_size)
{
    __shared__ unsigned s_base;

    int tid = threadIdx.x;
    int wid = tid >> 5, lane = tid & 31;
    int bid = blockIdx.x;
    int grp = bid >> 6;
    int slot = bid & 63;
    int o0 = slot * 4;
    int b  = grp * 8 + wid;
    int p_role = lane & 3;

    if (tid == 0) s_base = *(volatile unsigned*)&g_flag[grp][slot];

    // loop-invariant registers: U rows (fp16), combined biases
    __half2 ureg[16][4];
    #pragma unroll
    for (int r = 0; r < 16; r++) {
        int p = r >> 2, gi = r & 3;
        int grow = gi * 256 + o0 + p;
        float4 u0 = *(const float4*)&Uw[(size_t)grow * 256 + lane * 8];
        float4 u1 = *(const float4*)&Uw[(size_t)grow * 256 + lane * 8 + 4];
        ureg[r][0] = __floats2half2_rn(u0.x, u0.y);
        ureg[r][1] = __floats2half2_rn(u0.z, u0.w);
        ureg[r][2] = __floats2half2_rn(u1.x, u1.y);
        ureg[r][3] = __floats2half2_rn(u1.z, u1.w);
    }
    float cbv[4], bbv;
    #pragma unroll
    for (int gi = 0; gi < 4; gi++) {
        int grow = gi * 256 + o0 + p_role;
        cbv[gi] = Wb[grow] + Ub[grow];
    }
    bbv = Bbias[o0 + p_role];

    float cc = 0.f;
    if (lane < 4) g_hh[0][b * 256 + o0 + lane] = __float2half(0.f);
    __syncthreads();
    unsigned base = s_base;
    if (tid == 0) {
        __threadfence();
        *(volatile unsigned*)&g_flag[grp][slot] = base + 1;
    }

    int pollidx = tid & 63;
    const volatile unsigned* myflag = &g_flag[grp][pollidx];

    for (int t = 0; t < T_DIM; t++) {
        // prefetch (in flight during barrier spin)
        uint4 pr[4];
        const __half* pp = g_P + (size_t)(b * T_DIM + t) * 65536 + (size_t)o0 * 256 + lane * 8;
        #pragma unroll
        for (int q = 0; q < 4; q++) pr[q] = *(const uint4*)(pp + (size_t)q * 256);
        float wxv[4];
        if (lane < 4) {
            const __half* wp = g_Wxh + (size_t)(b * T_DIM + t) * 1024 + o0 + lane;
            #pragma unroll
            for (int gi = 0; gi < 4; gi++) wxv[gi] = __half2float(wp[gi * 256]);
        }

        // barrier: all peer blocks wrote h(t-1)
        {
            unsigned target = base + 1 + (unsigned)t;
            bool ok;
            do {
                unsigned v = *myflag;
                ok = ((int)(v - target) >= 0);
            } while (!__syncthreads_and(ok));
            __threadfence();
        }

        int rb = t & 1;
        uint4 hv = *(const uint4*)&g_hh[rb][b * 256 + lane * 8];
        __half2 hh[4] = { *(__half2*)&hv.x, *(__half2*)&hv.y,
                          *(__half2*)&hv.z, *(__half2*)&hv.w };

        // U·h partials (fp16 chain of 8 -> fp32)
        float gs[16];
        #pragma unroll
        for (int r = 0; r < 16; r++) {
            __half2 a = __hmul2(ureg[r][0], hh[0]);
            a = __hfma2(ureg[r][1], hh[1], a);
            a = __hfma2(ureg[r][2], hh[2], a);
            a = __hfma2(ureg[r][3], hh[3], a);
            float2 f = __half22float2(a);
            gs[r] = f.x + f.y;
        }
        // P·h partials
        float ms[4];
        #pragma unroll
        for (int q = 0; q < 4; q++) {
            const __half2* pb = (const __half2*)&pr[q];
            __half2 a = __hmul2(pb[0], hh[0]);
            a = __hfma2(pb[1], hh[1], a);
            a = __hfma2(pb[2], hh[2], a);
            a = __hfma2(pb[3], hh[3], a);
            float2 f = __half22float2(a);
            ms[q] = f.x + f.y;
        }

        // value-parallel tree reduction: gs 16->1/lane (16 shfl)
        #pragma unroll
        for (int j = 0; j < 8; j++) {
            float send = (lane & 16) ? gs[j] : gs[j + 8];
            float recv = __shfl_xor_sync(0xffffffffu, send, 16);
            gs[j] = ((lane & 16) ? gs[j + 8] : gs[j]) + recv;
        }
        #pragma unroll
        for (int j = 0; j < 4; j++) {
            float send = (lane & 8) ? gs[j] : gs[j + 4];
            float recv = __shfl_xor_sync(0xffffffffu, send, 8);
            gs[j] = ((lane & 8) ? gs[j + 4] : gs[j]) + recv;
        }
        #pragma unroll
        for (int j = 0; j < 2; j++) {
            float send = (lane & 4) ? gs[j] : gs[j + 2];
            float recv = __shfl_xor_sync(0xffffffffu, send, 4);
            gs[j] = ((lane & 4) ? gs[j + 2] : gs[j]) + recv;
        }
        {
            float send = (lane & 2) ? gs[0] : gs[1];
            float recv = __shfl_xor_sync(0xffffffffu, send, 2);
            gs[0] = ((lane & 2) ? gs[1] : gs[0]) + recv;
            gs[0] += __shfl_xor_sync(0xffffffffu, gs[0], 1);
        }
        // ms 4->1/lane (6 shfl)
        #pragma unroll
        for (int j = 0; j < 2; j++) {
            float send = (lane & 16) ? ms[j] : ms[j + 2];
            float recv = __shfl_xor_sync(0xffffffffu, send, 16);
            ms[j] = ((lane & 16) ? ms[j + 2] : ms[j]) + recv;
        }
        {
            float send = (lane & 8) ? ms[0] : ms[1];
            float recv = __shfl_xor_sync(0xffffffffu, send, 8);
            ms[0] = ((lane & 8) ? ms[1] : ms[0]) + recv;
            ms[0] += __shfl_xor_sync(0xffffffffu, ms[0], 4);
            ms[0] += __shfl_xor_sync(0xffffffffu, ms[0], 2);
            ms[0] += __shfl_xor_sync(0xffffffffu, ms[0], 1);
        }
        // gather: lane p pulls its 4 gate sums + ms (5 shfl)
        float gate[4];
        #pragma unroll
        for (int gi = 0; gi < 4; gi++) {
            int I = p_role * 4 + gi;
            int s = ((I >> 3) << 4) | (((I >> 2) & 1) << 3) | (((I >> 1) & 1) << 2) | ((I & 1) << 1);
            gate[gi] = __shfl_sync(0xffffffffu, gs[0], s);
        }
        float msv;
        {
            int s = ((p_role >> 1) << 4) | ((p_role & 1) << 3);
            msv = __shfl_sync(0xffffffffu, ms[0], s);
        }

        if (lane < 4) {
            float iv = sigmoid_fast(gate[0] + wxv[0] + cbv[0]);
            float fv = sigmoid_fast(gate[1] + wxv[1] + cbv[1]);
            float ov = sigmoid_fast(gate[2] + wxv[2] + cbv[2]);
            float gv = tanh_fast(gate[3] + wxv[3] + cbv[3]);
            float mv = tanh_fast(msv + bbv);
            cc = fv * cc + iv * gv + SCALE_C * mv;
            float hn = ov * tanh_fast(cc);
            g_hh[rb ^ 1][b * 256 + o0 + lane] = __float2half(hn);
            out[((size_t)b * T_DIM + t) * 256 + o0 + lane] = hn;
            if (t == T_DIM - 1) {
                size_t tail = (size_t)B_DIM * T_DIM * H_DIM;
                if (out_size >= (int)(tail + 2 * B_DIM * H_DIM)) {
                    out[tail + b * 256 + o0 + lane] = hn;
                    out[tail + B_DIM * H_DIM + b * 256 + o0 + lane] = cc;
                }
            }
        }

        __syncthreads();
        if (tid == 0) {
            __threadfence();
            *(volatile unsigned*)&g_flag[grp][slot] = base + 2 + (unsigned)t;
        }
    }
}

// ---------------- launch ----------------
extern "C" void kernel_launch(void* const* d_in, const int* in_sizes, int n_in,
                              void* d_out, int out_size) {
    const float* x  = (const float*)d_in[0];
    const float* Ww = (const float*)d_in[1];
    const float* Wb = (const float*)d_in[2];
    const float* Uw = (const float*)d_in[3];
    const float* Ub = (const float*)d_in[4];
    const float* Bw = (const float*)d_in[5];
    const float* Bb = (const float*)d_in[6];
    float* out = (float*)d_out;

    cudaFuncSetAttribute(gemm_P_kernel, cudaFuncAttributeMaxDynamicSharedMemorySize, SMEM_DYN);

    cvt_x_kernel<<<1024, 512>>>(x, Ww);
    transpose_B_kernel<<<dim3(8, 8, 256), dim3(32, 8)>>>(Bw);
    gemm_P_kernel<<<dim3(64, 520), 256, SMEM_DYN>>>();
    scan_kernel<<<128, 256>>>(Uw, Wb, Ub, Bb, out, out_size);
}